// round 1
// baseline (speedup 1.0000x reference)
#include <cuda_runtime.h>

#define NN 50000
#define NE 800000
#define DD 64

// scratch (no allocations allowed)
__device__ float g_agg[NN * DD];
__device__ float g_y0[NN * DD];

// ---------------------------------------------------------------------------
// zero the aggregation buffer
// ---------------------------------------------------------------------------
__global__ void zero_agg_kernel() {
    int i = blockIdx.x * blockDim.x + threadIdx.x;
    if (i < NN * DD / 4) {
        ((float4*)g_agg)[i] = make_float4(0.f, 0.f, 0.f, 0.f);
    }
}

// ---------------------------------------------------------------------------
// edge scatter: agg[dst[e]] += X[src[e]]   (X = x or g_y0)
// 16 threads per edge, each does one float4 gather + one red.global.v4
// ---------------------------------------------------------------------------
__global__ void scatter_kernel(const float* __restrict__ xin, int in_scratch,
                               const int* __restrict__ src,
                               const int* __restrict__ dst) {
    const float* __restrict__ base = in_scratch ? g_y0 : xin;
    int t = blockIdx.x * blockDim.x + threadIdx.x;
    int e = t >> 4;
    if (e >= NE) return;
    int q = (t & 15) << 2;  // float offset within the 64-float row

    int s = src[e];
    int d = dst[e];

    float4 v = *(const float4*)(base + (size_t)s * DD + q);
    float* p = g_agg + (size_t)d * DD + q;
    asm volatile("red.global.add.v4.f32 [%0], {%1,%2,%3,%4};"
                 :: "l"(p), "f"(v.x), "f"(v.y), "f"(v.z), "f"(v.w)
                 : "memory");
}

// ---------------------------------------------------------------------------
// fused MLP for one GIN layer:
//   out = tanh((X + agg) @ W1 + b1) @ W2 + b2
// block = 128 threads, 64 nodes per block, weights + node tiles in smem.
// Per-thread micro-tile: 4 nodes x 8 cols (32 accumulators).
// ---------------------------------------------------------------------------
__device__ __forceinline__ float fast_tanh(float x) {
    float y;
    asm("tanh.approx.f32 %0, %1;" : "=f"(y) : "f"(x));
    return y;
}

#define T_STRIDE 65  // padded row stride for node tiles (bank-conflict relief)

__global__ void __launch_bounds__(128, 2)
mlp_kernel(const float* __restrict__ xin, int in_scratch,
           const float* __restrict__ w1, const float* __restrict__ b1,
           const float* __restrict__ w2, const float* __restrict__ b2,
           float* __restrict__ out, int out_scratch) {
    extern __shared__ float sm[];
    float* sW1 = sm;                    // 64*64
    float* sW2 = sm + 4096;             // 64*64
    float* sT  = sm + 8192;             // 64 * T_STRIDE
    float* sH  = sT + 64 * T_STRIDE;    // 64 * T_STRIDE

    const float* __restrict__ xi = in_scratch ? g_y0 : xin;
    float* __restrict__ o = out_scratch ? g_y0 : out;

    const int tid = threadIdx.x;
    const int n0 = blockIdx.x * 64;

    // ---- load weights into smem (coalesced float4) ----
    #pragma unroll
    for (int rep = 0; rep < 8; rep++) {
        int f4 = rep * 128 + tid;
        ((float4*)sW1)[f4] = ((const float4*)w1)[f4];
        ((float4*)sW2)[f4] = ((const float4*)w2)[f4];
    }

    // ---- load node tile t = x + agg into sT (row-major, padded stride) ----
    #pragma unroll
    for (int rep = 0; rep < 8; rep++) {
        int f4 = rep * 128 + tid;      // 0..1023 float4 index over 64x64 tile
        int n = f4 >> 4;
        int k = (f4 & 15) << 2;
        float4 v;
        if (n0 + n < NN) {
            const float4 a = *(const float4*)(xi + (size_t)(n0 + n) * DD + k);
            const float4 g = *(const float4*)(g_agg + (size_t)(n0 + n) * DD + k);
            v = make_float4(a.x + g.x, a.y + g.y, a.z + g.z, a.w + g.w);
        } else {
            v = make_float4(0.f, 0.f, 0.f, 0.f);
        }
        float* p = sT + n * T_STRIDE + k;
        p[0] = v.x; p[1] = v.y; p[2] = v.z; p[3] = v.w;
    }
    __syncthreads();

    const int ng = tid & 15;   // node group (4 nodes)
    const int cg = tid >> 4;   // col group (8 cols)
    const int nb = ng * 4;
    const int cb = cg * 8;

    float acc[4][8];

    // ---- GEMM1: h = t @ W1 + b1 ----
    {
        float bv[8];
        #pragma unroll
        for (int u = 0; u < 8; u++) bv[u] = b1[cb + u];
        #pragma unroll
        for (int j = 0; j < 4; j++)
            #pragma unroll
            for (int u = 0; u < 8; u++) acc[j][u] = bv[u];

        #pragma unroll 4
        for (int k = 0; k < 64; k++) {
            float4 wA = *(const float4*)(sW1 + k * 64 + cb);
            float4 wB = *(const float4*)(sW1 + k * 64 + cb + 4);
            float w[8] = {wA.x, wA.y, wA.z, wA.w, wB.x, wB.y, wB.z, wB.w};
            #pragma unroll
            for (int j = 0; j < 4; j++) {
                float tv = sT[(nb + j) * T_STRIDE + k];
                #pragma unroll
                for (int u = 0; u < 8; u++) acc[j][u] += tv * w[u];
            }
        }
    }

    // ---- tanh + stage h in smem ----
    #pragma unroll
    for (int j = 0; j < 4; j++)
        #pragma unroll
        for (int u = 0; u < 8; u++)
            sH[(nb + j) * T_STRIDE + cb + u] = fast_tanh(acc[j][u]);
    __syncthreads();

    // ---- GEMM2: y = h @ W2 + b2 ----
    {
        float bv[8];
        #pragma unroll
        for (int u = 0; u < 8; u++) bv[u] = b2[cb + u];
        #pragma unroll
        for (int j = 0; j < 4; j++)
            #pragma unroll
            for (int u = 0; u < 8; u++) acc[j][u] = bv[u];

        #pragma unroll 4
        for (int k = 0; k < 64; k++) {
            float4 wA = *(const float4*)(sW2 + k * 64 + cb);
            float4 wB = *(const float4*)(sW2 + k * 64 + cb + 4);
            float w[8] = {wA.x, wA.y, wA.z, wA.w, wB.x, wB.y, wB.z, wB.w};
            #pragma unroll
            for (int j = 0; j < 4; j++) {
                float hv = sH[(nb + j) * T_STRIDE + k];
                #pragma unroll
                for (int u = 0; u < 8; u++) acc[j][u] += hv * w[u];
            }
        }
    }

    // ---- store outputs ----
    #pragma unroll
    for (int j = 0; j < 4; j++) {
        int n = n0 + nb + j;
        if (n < NN) {
            float4 o1 = make_float4(acc[j][0], acc[j][1], acc[j][2], acc[j][3]);
            float4 o2 = make_float4(acc[j][4], acc[j][5], acc[j][6], acc[j][7]);
            *(float4*)(o + (size_t)n * DD + cb) = o1;
            *(float4*)(o + (size_t)n * DD + cb + 4) = o2;
        }
    }
}

// ---------------------------------------------------------------------------
// launch
// ---------------------------------------------------------------------------
extern "C" void kernel_launch(void* const* d_in, const int* in_sizes, int n_in,
                              void* d_out, int out_size) {
    const float* x    = (const float*)d_in[0];
    const int*   src  = (const int*)d_in[1];
    const int*   dst  = (const int*)d_in[2];
    const float* w1_0 = (const float*)d_in[3];
    const float* b1_0 = (const float*)d_in[4];
    const float* w2_0 = (const float*)d_in[5];
    const float* b2_0 = (const float*)d_in[6];
    const float* w1_1 = (const float*)d_in[7];
    const float* b1_1 = (const float*)d_in[8];
    const float* w2_1 = (const float*)d_in[9];
    const float* b2_1 = (const float*)d_in[10];
    float* out = (float*)d_out;

    const int smem_bytes = (4096 * 2 + 64 * T_STRIDE * 2) * sizeof(float);
    cudaFuncSetAttribute(mlp_kernel, cudaFuncAttributeMaxDynamicSharedMemorySize,
                         smem_bytes);

    const int zero_blocks = (NN * DD / 4 + 255) / 256;      // 3125
    const int scat_blocks = (NE * 16 + 255) / 256;          // 50000
    const int mlp_blocks  = (NN + 63) / 64;                 // 782

    // ---- layer 0 ----
    zero_agg_kernel<<<zero_blocks, 256>>>();
    scatter_kernel<<<scat_blocks, 256>>>(x, 0, src, dst);
    mlp_kernel<<<mlp_blocks, 128, smem_bytes>>>(x, 0, w1_0, b1_0, w2_0, b2_0,
                                                out, /*out_scratch=*/1);

    // ---- layer 1 ----
    zero_agg_kernel<<<zero_blocks, 256>>>();
    scatter_kernel<<<scat_blocks, 256>>>(nullptr, 1, src, dst);
    mlp_kernel<<<mlp_blocks, 128, smem_bytes>>>(nullptr, 1, w1_1, b1_1, w2_1, b2_1,
                                                out, /*out_scratch=*/0);
}